// round 1
// baseline (speedup 1.0000x reference)
#include <cuda_runtime.h>
#include <cuda_bf16.h>
#include <math.h>

// ---------------- problem constants ----------------
constexpr int B_  = 4;
constexpr int T_  = 2048;
constexpr int S_  = 1024;
constexpr int C_  = 1024;
constexpr int E_  = 512;
constexpr int H_  = 16;
constexpr int D_  = 64;

constexpr int MQ = B_ * T_;   // 8192 rows (decoder side)
constexpr int ME = B_ * S_;   // 4096 rows (encoder side)

// ---------------- scratch (static device memory, no allocs) ----------------
__device__ float g_h  [ME * C_];   // gelu(enc_emb @ W1 + b1)
__device__ float g_tmp[ME * C_];   // h @ W2 + b2 (pre-LN)
__device__ float g_enc[ME * C_];   // layernorm result
__device__ float g_q  [MQ * C_];
__device__ float g_k  [ME * C_];
__device__ float g_v  [ME * C_];
__device__ float g_y  [MQ * C_];

// ---------------- SGEMM: C = A[M,K] @ B[K,N] + bias, optional GELU ---------
constexpr int BM = 128, BN = 128, BK = 8, TM = 8, TN = 8;

__global__ __launch_bounds__(256)
void sgemm_bias(const float* __restrict__ A, const float* __restrict__ Bm,
                const float* __restrict__ bias, float* __restrict__ C,
                int M, int N, int K, int act)   // act: 0 = bias only, 1 = bias+GELU(exact)
{
    __shared__ float As[BK][BM];
    __shared__ float Bs[BK][BN];

    const int tid  = threadIdx.x;
    const int tRow = tid >> 4;          // 0..15
    const int tCol = tid & 15;          // 0..15

    const int aRow = tid >> 1;          // 0..127
    const int aCol = (tid & 1) * 4;     // 0 or 4
    const int bRow = tid >> 5;          // 0..7
    const int bCol = (tid & 31) * 4;    // 0..124

    const float* Ab = A + (size_t)blockIdx.y * BM * K;
    const float* Bb = Bm + (size_t)blockIdx.x * BN;

    float acc[TM][TN];
    #pragma unroll
    for (int i = 0; i < TM; i++)
        #pragma unroll
        for (int j = 0; j < TN; j++) acc[i][j] = 0.f;

    for (int k0 = 0; k0 < K; k0 += BK) {
        float4 a4 = *(const float4*)(Ab + (size_t)aRow * K + k0 + aCol);
        As[aCol + 0][aRow] = a4.x;
        As[aCol + 1][aRow] = a4.y;
        As[aCol + 2][aRow] = a4.z;
        As[aCol + 3][aRow] = a4.w;
        *(float4*)&Bs[bRow][bCol] = *(const float4*)(Bb + (size_t)(k0 + bRow) * N + bCol);
        __syncthreads();

        #pragma unroll
        for (int kk = 0; kk < BK; kk++) {
            float4 m0 = *(const float4*)&As[kk][tRow * TM];
            float4 m1 = *(const float4*)&As[kk][tRow * TM + 4];
            float4 n0 = *(const float4*)&Bs[kk][tCol * TN];
            float4 n1 = *(const float4*)&Bs[kk][tCol * TN + 4];
            float regM[TM] = {m0.x, m0.y, m0.z, m0.w, m1.x, m1.y, m1.z, m1.w};
            float regN[TN] = {n0.x, n0.y, n0.z, n0.w, n1.x, n1.y, n1.z, n1.w};
            #pragma unroll
            for (int i = 0; i < TM; i++)
                #pragma unroll
                for (int j = 0; j < TN; j++)
                    acc[i][j] += regM[i] * regN[j];
        }
        __syncthreads();
    }

    // epilogue: bias (+ exact GELU), vectorized store
    #pragma unroll
    for (int i = 0; i < TM; i++) {
        const size_t r = (size_t)blockIdx.y * BM + tRow * TM + i;
        #pragma unroll
        for (int j = 0; j < TN; j += 4) {
            const int c = blockIdx.x * BN + tCol * TN + j;
            float4 o;
            o.x = acc[i][j + 0] + bias[c + 0];
            o.y = acc[i][j + 1] + bias[c + 1];
            o.z = acc[i][j + 2] + bias[c + 2];
            o.w = acc[i][j + 3] + bias[c + 3];
            if (act == 1) {
                o.x = 0.5f * o.x * (1.f + erff(o.x * 0.70710678118654752f));
                o.y = 0.5f * o.y * (1.f + erff(o.y * 0.70710678118654752f));
                o.z = 0.5f * o.z * (1.f + erff(o.z * 0.70710678118654752f));
                o.w = 0.5f * o.w * (1.f + erff(o.w * 0.70710678118654752f));
            }
            *(float4*)(C + r * N + c) = o;
        }
    }
}

// ---------------- LayerNorm over last dim (C=1024), one block per row ------
__global__ __launch_bounds__(256)
void ln_kernel(const float* __restrict__ in, const float* __restrict__ g,
               const float* __restrict__ b, float* __restrict__ out)
{
    const int row = blockIdx.x;
    const int tid = threadIdx.x;
    float4 v = ((const float4*)(in + (size_t)row * C_))[tid];

    float s  = v.x + v.y + v.z + v.w;
    float s2 = v.x * v.x + v.y * v.y + v.z * v.z + v.w * v.w;
    #pragma unroll
    for (int off = 16; off > 0; off >>= 1) {
        s  += __shfl_xor_sync(0xffffffffu, s,  off);
        s2 += __shfl_xor_sync(0xffffffffu, s2, off);
    }
    __shared__ float sh[16];
    const int w = tid >> 5;
    if ((tid & 31) == 0) { sh[w] = s; sh[w + 8] = s2; }
    __syncthreads();
    if (tid < 32) {
        float a  = (tid < 8) ? sh[tid]     : 0.f;
        float a2 = (tid < 8) ? sh[tid + 8] : 0.f;
        #pragma unroll
        for (int off = 4; off > 0; off >>= 1) {
            a  += __shfl_xor_sync(0xffffffffu, a,  off);
            a2 += __shfl_xor_sync(0xffffffffu, a2, off);
        }
        if (tid == 0) { sh[0] = a; sh[1] = a2; }
    }
    __syncthreads();
    const float mu   = sh[0] * (1.f / C_);
    const float var  = sh[1] * (1.f / C_) - mu * mu;
    const float rstd = rsqrtf(var + 1e-5f);

    float4 gg = ((const float4*)g)[tid];
    float4 bb = ((const float4*)b)[tid];
    float4 o;
    o.x = (v.x - mu) * rstd * gg.x + bb.x;
    o.y = (v.y - mu) * rstd * gg.y + bb.y;
    o.z = (v.z - mu) * rstd * gg.z + bb.z;
    o.w = (v.w - mu) * rstd * gg.w + bb.w;
    ((float4*)(out + (size_t)row * C_))[tid] = o;
}

// ---------------- Fused flash attention -----------------------------------
// grid (T/64, H, B), 256 threads (16x16). 64-query x 32-key tiles, D=64.
constexpr int ABM = 64, ABS = 32;

__global__ __launch_bounds__(256)
void attn_kernel(const float* __restrict__ Q, const float* __restrict__ K,
                 const float* __restrict__ V, const int* __restrict__ mask,
                 float* __restrict__ Y)
{
    __shared__ float Qs[ABM][68];
    __shared__ float Ks[ABS][68];
    __shared__ float Vs[ABS][68];
    __shared__ float Ps[ABM][36];

    const int b  = blockIdx.z, h = blockIdx.y;
    const int t0 = blockIdx.x * ABM;
    const int tid = threadIdx.x;
    const int ty = tid >> 4, tx = tid & 15;

    const float* Qb = Q + ((size_t)(b * T_ + t0)) * C_ + h * D_;
    const float* Kb = K + ((size_t)(b * S_)) * C_ + h * D_;
    const float* Vb = V + ((size_t)(b * S_)) * C_ + h * D_;
    const int*   mb = mask + b * S_;

    // load Q tile (64x64), float4, coalesced
    for (int idx = tid; idx < ABM * (D_ / 4); idx += 256) {
        int r = idx >> 4, c4 = (idx & 15) * 4;
        *(float4*)&Qs[r][c4] = *(const float4*)(Qb + (size_t)r * C_ + c4);
    }

    float m[4], l[4], o[4][4];
    #pragma unroll
    for (int i = 0; i < 4; i++) {
        m[i] = -INFINITY; l[i] = 0.f;
        #pragma unroll
        for (int j = 0; j < 4; j++) o[i][j] = 0.f;
    }
    __syncthreads();

    for (int s0 = 0; s0 < S_; s0 += ABS) {
        for (int idx = tid; idx < ABS * (D_ / 4); idx += 256) {
            int r = idx >> 4, c4 = (idx & 15) * 4;
            *(float4*)&Ks[r][c4] = *(const float4*)(Kb + (size_t)(s0 + r) * C_ + c4);
            *(float4*)&Vs[r][c4] = *(const float4*)(Vb + (size_t)(s0 + r) * C_ + c4);
        }
        __syncthreads();

        // scores: rows ty*4+i (4), cols tx*2+j (2)
        float sc[4][2] = {{0.f, 0.f}, {0.f, 0.f}, {0.f, 0.f}, {0.f, 0.f}};
        #pragma unroll
        for (int d0 = 0; d0 < D_; d0 += 4) {
            float4 q4[4], k4[2];
            #pragma unroll
            for (int i = 0; i < 4; i++) q4[i] = *(const float4*)&Qs[ty * 4 + i][d0];
            #pragma unroll
            for (int j = 0; j < 2; j++) k4[j] = *(const float4*)&Ks[tx * 2 + j][d0];
            #pragma unroll
            for (int i = 0; i < 4; i++)
                #pragma unroll
                for (int j = 0; j < 2; j++)
                    sc[i][j] += q4[i].x * k4[j].x + q4[i].y * k4[j].y +
                                q4[i].z * k4[j].z + q4[i].w * k4[j].w;
        }

        const int ok0 = mb[s0 + tx * 2];
        const int ok1 = mb[s0 + tx * 2 + 1];
        #pragma unroll
        for (int i = 0; i < 4; i++) {
            sc[i][0] = ok0 ? sc[i][0] * 0.125f : -INFINITY;
            sc[i][1] = ok1 ? sc[i][1] * 0.125f : -INFINITY;
        }

        // online softmax update (row groups = 16 lanes sharing ty)
        #pragma unroll
        for (int i = 0; i < 4; i++) {
            float mt = fmaxf(sc[i][0], sc[i][1]);
            #pragma unroll
            for (int off = 8; off > 0; off >>= 1)
                mt = fmaxf(mt, __shfl_xor_sync(0xffffffffu, mt, off, 16));
            const float mn    = fmaxf(m[i], mt);
            const float alpha = __expf(m[i] - mn);
            const float p0 = __expf(sc[i][0] - mn);
            const float p1 = __expf(sc[i][1] - mn);
            Ps[ty * 4 + i][tx * 2 + 0] = p0;
            Ps[ty * 4 + i][tx * 2 + 1] = p1;
            float rs = p0 + p1;
            #pragma unroll
            for (int off = 8; off > 0; off >>= 1)
                rs += __shfl_xor_sync(0xffffffffu, rs, off, 16);
            l[i] = l[i] * alpha + rs;
            m[i] = mn;
            #pragma unroll
            for (int j = 0; j < 4; j++) o[i][j] *= alpha;
        }
        __syncthreads();

        // O += P @ V   (d = tx*4 + j, vectorized V read)
        #pragma unroll 4
        for (int s = 0; s < ABS; s++) {
            float4 v4 = *(const float4*)&Vs[s][tx * 4];
            float pv[4];
            #pragma unroll
            for (int i = 0; i < 4; i++) pv[i] = Ps[ty * 4 + i][s];
            #pragma unroll
            for (int i = 0; i < 4; i++) {
                o[i][0] += pv[i] * v4.x;
                o[i][1] += pv[i] * v4.y;
                o[i][2] += pv[i] * v4.z;
                o[i][3] += pv[i] * v4.w;
            }
        }
        __syncthreads();
    }

    float* Yb = Y + ((size_t)(b * T_ + t0)) * C_ + h * D_;
    #pragma unroll
    for (int i = 0; i < 4; i++) {
        const float inv = 1.f / l[i];
        float4 o4 = make_float4(o[i][0] * inv, o[i][1] * inv, o[i][2] * inv, o[i][3] * inv);
        *(float4*)(Yb + (size_t)(ty * 4 + i) * C_ + tx * 4) = o4;
    }
}

// ---------------- launcher -------------------------------------------------
extern "C" void kernel_launch(void* const* d_in, const int* in_sizes, int n_in,
                              void* d_out, int out_size)
{
    const float* x    = (const float*)d_in[0];
    const float* eemb = (const float*)d_in[1];
    const int*   emsk = (const int*)  d_in[2];
    const float* W1   = (const float*)d_in[3];
    const float* b1   = (const float*)d_in[4];
    const float* W2   = (const float*)d_in[5];
    const float* b2   = (const float*)d_in[6];
    const float* lng  = (const float*)d_in[7];
    const float* lnb  = (const float*)d_in[8];
    const float* Wq   = (const float*)d_in[9];
    const float* bq   = (const float*)d_in[10];
    const float* Wk   = (const float*)d_in[11];
    const float* bk   = (const float*)d_in[12];
    const float* Wv   = (const float*)d_in[13];
    const float* bv   = (const float*)d_in[14];
    const float* Wp   = (const float*)d_in[15];
    const float* bp   = (const float*)d_in[16];
    float* out = (float*)d_out;

    float *h, *tmp, *enc, *q, *k, *v, *y;
    cudaGetSymbolAddress((void**)&h,   g_h);
    cudaGetSymbolAddress((void**)&tmp, g_tmp);
    cudaGetSymbolAddress((void**)&enc, g_enc);
    cudaGetSymbolAddress((void**)&q,   g_q);
    cudaGetSymbolAddress((void**)&k,   g_k);
    cudaGetSymbolAddress((void**)&v,   g_v);
    cudaGetSymbolAddress((void**)&y,   g_y);

    const dim3 blk(256);

    // enc MLP
    sgemm_bias<<<dim3(C_ / BN, ME / BM), blk>>>(eemb, W1, b1, h, ME, C_, E_, 1);
    sgemm_bias<<<dim3(C_ / BN, ME / BM), blk>>>(h, W2, b2, tmp, ME, C_, C_, 0);
    ln_kernel<<<ME, blk>>>(tmp, lng, lnb, enc);

    // projections
    sgemm_bias<<<dim3(C_ / BN, MQ / BM), blk>>>(x,   Wq, bq, q, MQ, C_, C_, 0);
    sgemm_bias<<<dim3(C_ / BN, ME / BM), blk>>>(enc, Wk, bk, k, ME, C_, C_, 0);
    sgemm_bias<<<dim3(C_ / BN, ME / BM), blk>>>(enc, Wv, bv, v, ME, C_, C_, 0);

    // fused attention
    attn_kernel<<<dim3(T_ / ABM, H_, B_), blk>>>(q, k, v, emsk, y);

    // output projection
    sgemm_bias<<<dim3(C_ / BN, MQ / BM), blk>>>(y, Wp, bp, out, MQ, C_, C_, 0);
}

// round 3
// speedup vs baseline: 1.4870x; 1.4870x over previous
#include <cuda_runtime.h>
#include <cuda_bf16.h>
#include <math.h>
#include <stdint.h>

// ---------------- problem constants ----------------
constexpr int B_  = 4;
constexpr int T_  = 2048;
constexpr int S_  = 1024;
constexpr int C_  = 1024;
constexpr int E_  = 512;
constexpr int H_  = 16;
constexpr int D_  = 64;

constexpr int MQ = B_ * T_;   // 8192
constexpr int ME = B_ * S_;   // 4096

// ---------------- scratch ----------------
__device__ float g_h  [ME * C_];
__device__ float g_tmp[ME * C_];
__device__ float g_enc[ME * C_];
__device__ float g_q  [MQ * C_];
__device__ float g_k  [ME * C_];
__device__ float g_v  [ME * C_];
__device__ float g_y  [MQ * C_];
__device__ float g_w1t[C_ * E_];
__device__ float g_w2t[C_ * C_];
__device__ float g_wqt[C_ * C_];
__device__ float g_wkt[C_ * C_];
__device__ float g_wvt[C_ * C_];
__device__ float g_wpt[C_ * C_];

// ---------------- helpers ----------------
__device__ __forceinline__ uint32_t smem_u32(const void* p) {
    uint32_t a;
    asm("{ .reg .u64 t; cvta.to.shared.u64 t, %1; cvt.u32.u64 %0, t; }" : "=r"(a) : "l"(p));
    return a;
}

__device__ __forceinline__ void ldmx4(uint32_t* r, uint32_t addr) {
    asm volatile("ldmatrix.sync.aligned.m8n8.x4.shared.b16 {%0,%1,%2,%3}, [%4];"
                 : "=r"(r[0]), "=r"(r[1]), "=r"(r[2]), "=r"(r[3]) : "r"(addr));
}

#define MMA_BF16(acc, a, b0, b1)                                              \
    asm volatile(                                                             \
        "mma.sync.aligned.m16n8k16.row.col.f32.bf16.bf16.f32 "                \
        "{%0,%1,%2,%3},{%4,%5,%6,%7},{%8,%9},{%0,%1,%2,%3};"                  \
        : "+f"((acc)[0]), "+f"((acc)[1]), "+f"((acc)[2]), "+f"((acc)[3])      \
        : "r"((a)[0]), "r"((a)[1]), "r"((a)[2]), "r"((a)[3]),                 \
          "r"(b0), "r"(b1))

__device__ __forceinline__ float gelu_f(float x) {
    return 0.5f * x * (1.f + erff(x * 0.70710678118654752f));
}

// pack float4 into hi/lo bf16 pairs
__device__ __forceinline__ void split_f4(float4 v, uint32_t& h0, uint32_t& h1,
                                         uint32_t& l0, uint32_t& l1)
{
    __nv_bfloat16 hx = __float2bfloat16(v.x);
    __nv_bfloat16 hy = __float2bfloat16(v.y);
    __nv_bfloat16 hz = __float2bfloat16(v.z);
    __nv_bfloat16 hw = __float2bfloat16(v.w);
    __nv_bfloat162 hp0 = __halves2bfloat162(hx, hy);
    __nv_bfloat162 hp1 = __halves2bfloat162(hz, hw);
    __nv_bfloat162 lp0 = __floats2bfloat162_rn(v.x - __bfloat162float(hx),
                                               v.y - __bfloat162float(hy));
    __nv_bfloat162 lp1 = __floats2bfloat162_rn(v.z - __bfloat162float(hz),
                                               v.w - __bfloat162float(hw));
    h0 = *reinterpret_cast<uint32_t*>(&hp0);
    h1 = *reinterpret_cast<uint32_t*>(&hp1);
    l0 = *reinterpret_cast<uint32_t*>(&lp0);
    l1 = *reinterpret_cast<uint32_t*>(&lp1);
}

__device__ __forceinline__ void sts_v2(uint32_t addr, uint32_t a, uint32_t b) {
    asm volatile("st.shared.v2.b32 [%0], {%1, %2};" :: "r"(addr), "r"(a), "r"(b) : "memory");
}

// ---------------- HMMA GEMM: C = A[M,K] @ Bt[N,K]^T + bias (+GELU) --------
// 128x128 tile, KC=32 fp32 per chunk as hi/lo bf16, double-buffered.
// smem stage layout (row stride 80B, 128 rows each):
//   A_hi[0,10240) A_lo[10240,20480) B_hi[20480,30720) B_lo[30720,40960)
constexpr uint32_t RSB        = 80;        // bytes per smem row (32 bf16 + 16B pad)
constexpr uint32_t TILE_B     = 128 * RSB; // 10240
constexpr uint32_t STAGE      = 4 * TILE_B;
constexpr uint32_t GEMM_SMEM  = 2 * STAGE; // 81920

__global__ __launch_bounds__(256)
void gemm_mma(const float* __restrict__ A, const float* __restrict__ Bt,
              const float* __restrict__ bias, float* __restrict__ Cout,
              int M, int N, int K, int act)
{
    extern __shared__ char smem[];
    const uint32_t sb = smem_u32(smem);
    const int tid  = threadIdx.x;
    const int lane = tid & 31;
    const int wid  = tid >> 5;
    const int wm   = wid & 3;     // warp M block (32 rows)
    const int wn   = wid >> 2;    // warp N block (64 cols)
    const int m0   = blockIdx.y * 128;
    const int n0   = blockIdx.x * 128;

    // global load mapping: 4 float4 per matrix per thread per chunk
    const int q  = tid & 7;       // float4 index in 32-float row chunk
    const int r0 = tid >> 3;      // rows r0 + 32j

    float acc[2][8][4];
    #pragma unroll
    for (int i = 0; i < 2; i++)
        #pragma unroll
        for (int j = 0; j < 8; j++)
            #pragma unroll
            for (int t = 0; t < 4; t++) acc[i][j][t] = 0.f;

    const int NC = K >> 5;

    // ---- load chunk 0 into stage 0 ----
    {
        const float* Ap = A  + (size_t)(m0 + r0) * K + q * 4;
        const float* Bp = Bt + (size_t)(n0 + r0) * K + q * 4;
        #pragma unroll
        for (int j = 0; j < 4; j++) {
            float4 av = *(const float4*)(Ap + (size_t)j * 32 * K);
            float4 bv = *(const float4*)(Bp + (size_t)j * 32 * K);
            uint32_t h0, h1, l0, l1;
            uint32_t off = (uint32_t)(r0 + 32 * j) * RSB + q * 8;
            split_f4(av, h0, h1, l0, l1);
            sts_v2(sb + off, h0, h1);
            sts_v2(sb + TILE_B + off, l0, l1);
            split_f4(bv, h0, h1, l0, l1);
            sts_v2(sb + 2 * TILE_B + off, h0, h1);
            sts_v2(sb + 3 * TILE_B + off, l0, l1);
        }
    }
    __syncthreads();

    // ldmatrix lane addressing
    const uint32_t arow  = lane & 15;
    const uint32_t akoff = (lane >> 4) * 16;
    const uint32_t nrow  = (lane & 7) | ((lane >> 4) << 3);
    const uint32_t bkoff = ((lane >> 3) & 1) * 16;

    for (int c = 0; c < NC; c++) {
        const uint32_t st = sb + (uint32_t)(c & 1) * STAGE;
        const bool havenext = (c + 1 < NC);

        // prefetch next chunk
        float4 pa[4], pb[4];
        if (havenext) {
            const int k0 = (c + 1) << 5;
            const float* Ap = A  + (size_t)(m0 + r0) * K + k0 + q * 4;
            const float* Bp = Bt + (size_t)(n0 + r0) * K + k0 + q * 4;
            #pragma unroll
            for (int j = 0; j < 4; j++) {
                pa[j] = *(const float4*)(Ap + (size_t)j * 32 * K);
                pb[j] = *(const float4*)(Bp + (size_t)j * 32 * K);
            }
        }

        // compute chunk c
        #pragma unroll
        for (int kb = 0; kb < 2; kb++) {
            uint32_t ah[2][4], al[2][4];
            const uint32_t aBase = st + (wm * 32 + arow) * RSB + kb * 32 + akoff;
            #pragma unroll
            for (int mi = 0; mi < 2; mi++) {
                ldmx4(ah[mi], aBase + mi * 16 * RSB);
                ldmx4(al[mi], aBase + TILE_B + mi * 16 * RSB);
            }
            const uint32_t bBase = st + 2 * TILE_B + (wn * 64 + nrow) * RSB + kb * 32 + bkoff;
            #pragma unroll
            for (int np = 0; np < 4; np++) {
                uint32_t bh[4], bl[4];
                ldmx4(bh, bBase + np * 16 * RSB);
                ldmx4(bl, bBase + TILE_B + np * 16 * RSB);
                #pragma unroll
                for (int mi = 0; mi < 2; mi++) {
                    #pragma unroll
                    for (int t = 0; t < 2; t++) {
                        float* a4 = acc[mi][np * 2 + t];
                        MMA_BF16(a4, ah[mi], bh[2 * t], bh[2 * t + 1]);  // hi*hi
                        MMA_BF16(a4, ah[mi], bl[2 * t], bl[2 * t + 1]);  // hi*lo
                        MMA_BF16(a4, al[mi], bh[2 * t], bh[2 * t + 1]);  // lo*hi
                    }
                }
            }
        }

        if (havenext) {
            const uint32_t st2 = sb + (uint32_t)((c + 1) & 1) * STAGE;
            #pragma unroll
            for (int j = 0; j < 4; j++) {
                uint32_t h0, h1, l0, l1;
                uint32_t off = (uint32_t)(r0 + 32 * j) * RSB + q * 8;
                split_f4(pa[j], h0, h1, l0, l1);
                sts_v2(st2 + off, h0, h1);
                sts_v2(st2 + TILE_B + off, l0, l1);
                split_f4(pb[j], h0, h1, l0, l1);
                sts_v2(st2 + 2 * TILE_B + off, h0, h1);
                sts_v2(st2 + 3 * TILE_B + off, l0, l1);
            }
        }
        __syncthreads();
    }

    // ---- epilogue ----
    const int rbase = m0 + wm * 32 + (lane >> 2);
    const int cbase = n0 + wn * 64 + (lane & 3) * 2;
    #pragma unroll
    for (int mi = 0; mi < 2; mi++) {
        #pragma unroll
        for (int ni = 0; ni < 8; ni++) {
            const int col = cbase + ni * 8;
            const float bx = bias[col], by = bias[col + 1];
            const int r1 = rbase + mi * 16;
            float2 v0, v1;
            v0.x = acc[mi][ni][0] + bx;  v0.y = acc[mi][ni][1] + by;
            v1.x = acc[mi][ni][2] + bx;  v1.y = acc[mi][ni][3] + by;
            if (act == 1) {
                v0.x = gelu_f(v0.x); v0.y = gelu_f(v0.y);
                v1.x = gelu_f(v1.x); v1.y = gelu_f(v1.y);
            }
            *(float2*)(Cout + (size_t)r1 * N + col)       = v0;
            *(float2*)(Cout + (size_t)(r1 + 8) * N + col) = v1;
        }
    }
}

// ---------------- transpose W[R,Cc] -> Wt[Cc,R] ----------------------------
__global__ __launch_bounds__(256)
void transpose_kernel(const float* __restrict__ in, float* __restrict__ out,
                      int R, int Cc)
{
    __shared__ float t[32][33];
    const int bx = blockIdx.x * 32, by = blockIdx.y * 32;
    const int tx = threadIdx.x & 31, tyq = threadIdx.x >> 5;
    #pragma unroll
    for (int i = tyq; i < 32; i += 8)
        t[i][tx] = in[(size_t)(by + i) * Cc + bx + tx];
    __syncthreads();
    #pragma unroll
    for (int i = tyq; i < 32; i += 8)
        out[(size_t)(bx + i) * R + by + tx] = t[tx][i];
}

// ---------------- LayerNorm (C=1024), one block per row --------------------
__global__ __launch_bounds__(256)
void ln_kernel(const float* __restrict__ in, const float* __restrict__ g,
               const float* __restrict__ b, float* __restrict__ out)
{
    const int row = blockIdx.x;
    const int tid = threadIdx.x;
    float4 v = ((const float4*)(in + (size_t)row * C_))[tid];

    float s  = v.x + v.y + v.z + v.w;
    float s2 = v.x * v.x + v.y * v.y + v.z * v.z + v.w * v.w;
    #pragma unroll
    for (int off = 16; off > 0; off >>= 1) {
        s  += __shfl_xor_sync(0xffffffffu, s,  off);
        s2 += __shfl_xor_sync(0xffffffffu, s2, off);
    }
    __shared__ float sh[16];
    const int w = tid >> 5;
    if ((tid & 31) == 0) { sh[w] = s; sh[w + 8] = s2; }
    __syncthreads();
    if (tid < 32) {
        float a  = (tid < 8) ? sh[tid]     : 0.f;
        float a2 = (tid < 8) ? sh[tid + 8] : 0.f;
        #pragma unroll
        for (int off = 4; off > 0; off >>= 1) {
            a  += __shfl_xor_sync(0xffffffffu, a,  off);
            a2 += __shfl_xor_sync(0xffffffffu, a2, off);
        }
        if (tid == 0) { sh[0] = a; sh[1] = a2; }
    }
    __syncthreads();
    const float mu   = sh[0] * (1.f / C_);
    const float var  = sh[1] * (1.f / C_) - mu * mu;
    const float rstd = rsqrtf(var + 1e-5f);

    float4 gg = ((const float4*)g)[tid];
    float4 bb = ((const float4*)b)[tid];
    float4 o;
    o.x = (v.x - mu) * rstd * gg.x + bb.x;
    o.y = (v.y - mu) * rstd * gg.y + bb.y;
    o.z = (v.z - mu) * rstd * gg.z + bb.z;
    o.w = (v.w - mu) * rstd * gg.w + bb.w;
    ((float4*)(out + (size_t)row * C_))[tid] = o;
}

// ---------------- Fused flash attention (fp32 SIMT) ------------------------
constexpr int ABM = 64, ABS = 32;

__global__ __launch_bounds__(256)
void attn_kernel(const float* __restrict__ Q, const float* __restrict__ K,
                 const float* __restrict__ V, const int* __restrict__ mask,
                 float* __restrict__ Y)
{
    __shared__ float Qs[ABM][68];
    __shared__ float Ks[ABS][68];
    __shared__ float Vs[ABS][68];
    __shared__ float Ps[ABM][36];

    const int b  = blockIdx.z, h = blockIdx.y;
    const int t0 = blockIdx.x * ABM;
    const int tid = threadIdx.x;
    const int ty = tid >> 4, tx = tid & 15;

    const float* Qb = Q + ((size_t)(b * T_ + t0)) * C_ + h * D_;
    const float* Kb = K + ((size_t)(b * S_)) * C_ + h * D_;
    const float* Vb = V + ((size_t)(b * S_)) * C_ + h * D_;
    const int*   mb = mask + b * S_;

    for (int idx = tid; idx < ABM * (D_ / 4); idx += 256) {
        int r = idx >> 4, c4 = (idx & 15) * 4;
        *(float4*)&Qs[r][c4] = *(const float4*)(Qb + (size_t)r * C_ + c4);
    }

    float m[4], l[4], o[4][4];
    #pragma unroll
    for (int i = 0; i < 4; i++) {
        m[i] = -INFINITY; l[i] = 0.f;
        #pragma unroll
        for (int j = 0; j < 4; j++) o[i][j] = 0.f;
    }
    __syncthreads();

    for (int s0 = 0; s0 < S_; s0 += ABS) {
        for (int idx = tid; idx < ABS * (D_ / 4); idx += 256) {
            int r = idx >> 4, c4 = (idx & 15) * 4;
            *(float4*)&Ks[r][c4] = *(const float4*)(Kb + (size_t)(s0 + r) * C_ + c4);
            *(float4*)&Vs[r][c4] = *(const float4*)(Vb + (size_t)(s0 + r) * C_ + c4);
        }
        __syncthreads();

        float sc[4][2] = {{0.f, 0.f}, {0.f, 0.f}, {0.f, 0.f}, {0.f, 0.f}};
        #pragma unroll
        for (int d0 = 0; d0 < D_; d0 += 4) {
            float4 q4[4], k4[2];
            #pragma unroll
            for (int i = 0; i < 4; i++) q4[i] = *(const float4*)&Qs[ty * 4 + i][d0];
            #pragma unroll
            for (int j = 0; j < 2; j++) k4[j] = *(const float4*)&Ks[tx * 2 + j][d0];
            #pragma unroll
            for (int i = 0; i < 4; i++)
                #pragma unroll
                for (int j = 0; j < 2; j++)
                    sc[i][j] += q4[i].x * k4[j].x + q4[i].y * k4[j].y +
                                q4[i].z * k4[j].z + q4[i].w * k4[j].w;
        }

        const int ok0 = mb[s0 + tx * 2];
        const int ok1 = mb[s0 + tx * 2 + 1];
        #pragma unroll
        for (int i = 0; i < 4; i++) {
            sc[i][0] = ok0 ? sc[i][0] * 0.125f : -INFINITY;
            sc[i][1] = ok1 ? sc[i][1] * 0.125f : -INFINITY;
        }

        #pragma unroll
        for (int i = 0; i < 4; i++) {
            float mt = fmaxf(sc[i][0], sc[i][1]);
            #pragma unroll
            for (int off = 8; off > 0; off >>= 1)
                mt = fmaxf(mt, __shfl_xor_sync(0xffffffffu, mt, off, 16));
            const float mn    = fmaxf(m[i], mt);
            const float alpha = __expf(m[i] - mn);
            const float p0 = __expf(sc[i][0] - mn);
            const float p1 = __expf(sc[i][1] - mn);
            Ps[ty * 4 + i][tx * 2 + 0] = p0;
            Ps[ty * 4 + i][tx * 2 + 1] = p1;
            float rs = p0 + p1;
            #pragma unroll
            for (int off = 8; off > 0; off >>= 1)
                rs += __shfl_xor_sync(0xffffffffu, rs, off, 16);
            l[i] = l[i] * alpha + rs;
            m[i] = mn;
            #pragma unroll
            for (int j = 0; j < 4; j++) o[i][j] *= alpha;
        }
        __syncthreads();

        #pragma unroll 4
        for (int s = 0; s < ABS; s++) {
            float4 v4 = *(const float4*)&Vs[s][tx * 4];
            float pv[4];
            #pragma unroll
            for (int i = 0; i < 4; i++) pv[i] = Ps[ty * 4 + i][s];
            #pragma unroll
            for (int i = 0; i < 4; i++) {
                o[i][0] += pv[i] * v4.x;
                o[i][1] += pv[i] * v4.y;
                o[i][2] += pv[i] * v4.z;
                o[i][3] += pv[i] * v4.w;
            }
        }
        __syncthreads();
    }

    float* Yb = Y + ((size_t)(b * T_ + t0)) * C_ + h * D_;
    #pragma unroll
    for (int i = 0; i < 4; i++) {
        const float inv = 1.f / l[i];
        float4 o4 = make_float4(o[i][0] * inv, o[i][1] * inv, o[i][2] * inv, o[i][3] * inv);
        *(float4*)(Yb + (size_t)(ty * 4 + i) * C_ + tx * 4) = o4;
    }
}

// ---------------- launcher -------------------------------------------------
extern "C" void kernel_launch(void* const* d_in, const int* in_sizes, int n_in,
                              void* d_out, int out_size)
{
    const float* x    = (const float*)d_in[0];
    const float* eemb = (const float*)d_in[1];
    const int*   emsk = (const int*)  d_in[2];
    const float* W1   = (const float*)d_in[3];
    const float* b1   = (const float*)d_in[4];
    const float* W2   = (const float*)d_in[5];
    const float* b2   = (const float*)d_in[6];
    const float* lng  = (const float*)d_in[7];
    const float* lnb  = (const float*)d_in[8];
    const float* Wq   = (const float*)d_in[9];
    const float* bq   = (const float*)d_in[10];
    const float* Wk   = (const float*)d_in[11];
    const float* bk   = (const float*)d_in[12];
    const float* Wv   = (const float*)d_in[13];
    const float* bv   = (const float*)d_in[14];
    const float* Wp   = (const float*)d_in[15];
    const float* bp   = (const float*)d_in[16];
    float* out = (float*)d_out;

    float *h, *tmp, *enc, *q, *k, *v, *y;
    float *w1t, *w2t, *wqt, *wkt, *wvt, *wpt;
    cudaGetSymbolAddress((void**)&h,   g_h);
    cudaGetSymbolAddress((void**)&tmp, g_tmp);
    cudaGetSymbolAddress((void**)&enc, g_enc);
    cudaGetSymbolAddress((void**)&q,   g_q);
    cudaGetSymbolAddress((void**)&k,   g_k);
    cudaGetSymbolAddress((void**)&v,   g_v);
    cudaGetSymbolAddress((void**)&y,   g_y);
    cudaGetSymbolAddress((void**)&w1t, g_w1t);
    cudaGetSymbolAddress((void**)&w2t, g_w2t);
    cudaGetSymbolAddress((void**)&wqt, g_wqt);
    cudaGetSymbolAddress((void**)&wkt, g_wkt);
    cudaGetSymbolAddress((void**)&wvt, g_wvt);
    cudaGetSymbolAddress((void**)&wpt, g_wpt);

    cudaFuncSetAttribute(gemm_mma, cudaFuncAttributeMaxDynamicSharedMemorySize, GEMM_SMEM);

    // transpose weights -> [N, K]
    transpose_kernel<<<dim3(C_ / 32, E_ / 32), 256>>>(W1, w1t, E_, C_);
    transpose_kernel<<<dim3(C_ / 32, C_ / 32), 256>>>(W2, w2t, C_, C_);
    transpose_kernel<<<dim3(C_ / 32, C_ / 32), 256>>>(Wq, wqt, C_, C_);
    transpose_kernel<<<dim3(C_ / 32, C_ / 32), 256>>>(Wk, wkt, C_, C_);
    transpose_kernel<<<dim3(C_ / 32, C_ / 32), 256>>>(Wv, wvt, C_, C_);
    transpose_kernel<<<dim3(C_ / 32, C_ / 32), 256>>>(Wp, wpt, C_, C_);

    // encoder MLP
    gemm_mma<<<dim3(C_ / 128, ME / 128), 256, GEMM_SMEM>>>(eemb, w1t, b1, h, ME, C_, E_, 1);
    gemm_mma<<<dim3(C_ / 128, ME / 128), 256, GEMM_SMEM>>>(h, w2t, b2, tmp, ME, C_, C_, 0);
    ln_kernel<<<ME, 256>>>(tmp, lng, lnb, enc);

    // projections
    gemm_mma<<<dim3(C_ / 128, MQ / 128), 256, GEMM_SMEM>>>(x,   wqt, bq, q, MQ, C_, C_, 0);
    gemm_mma<<<dim3(C_ / 128, ME / 128), 256, GEMM_SMEM>>>(enc, wkt, bk, k, ME, C_, C_, 0);
    gemm_mma<<<dim3(C_ / 128, ME / 128), 256, GEMM_SMEM>>>(enc, wvt, bv, v, ME, C_, C_, 0);

    // attention
    attn_kernel<<<dim3(T_ / ABM, H_, B_), 256>>>(q, k, v, emsk, y);

    // output projection
    gemm_mma<<<dim3(C_ / 128, MQ / 128), 256, GEMM_SMEM>>>(y, wpt, bp, out, MQ, C_, C_, 0);
}

// round 4
// speedup vs baseline: 3.0440x; 2.0472x over previous
#include <cuda_runtime.h>
#include <cuda_bf16.h>
#include <math.h>
#include <stdint.h>

// ---------------- problem constants ----------------
constexpr int B_  = 4;
constexpr int T_  = 2048;
constexpr int S_  = 1024;
constexpr int C_  = 1024;
constexpr int E_  = 512;
constexpr int D_  = 64;

constexpr int MQ = B_ * T_;   // 8192
constexpr int ME = B_ * S_;   // 4096

// ---------------- scratch ----------------
__device__ float g_tmp[ME * C_];                       // pre-LN fp32

__device__ __nv_bfloat16 g_xh[MQ * C_],  g_xl[MQ * C_];
__device__ __nv_bfloat16 g_eh[ME * E_],  g_el[ME * E_];
__device__ __nv_bfloat16 g_hh[ME * C_],  g_hl[ME * C_];
__device__ __nv_bfloat16 g_ench[ME * C_],g_encl[ME * C_];
__device__ __nv_bfloat16 g_qh[MQ * C_],  g_ql[MQ * C_];
__device__ __nv_bfloat16 g_kh[ME * C_],  g_kl[ME * C_];
__device__ __nv_bfloat16 g_vh[ME * C_],  g_vl[ME * C_];
__device__ __nv_bfloat16 g_yh[MQ * C_],  g_yl[MQ * C_];
__device__ __nv_bfloat16 g_w1h[C_ * E_], g_w1l[C_ * E_];
__device__ __nv_bfloat16 g_w2h[C_ * C_], g_w2l[C_ * C_];
__device__ __nv_bfloat16 g_wqh[C_ * C_], g_wql[C_ * C_];
__device__ __nv_bfloat16 g_wkh[C_ * C_], g_wkl[C_ * C_];
__device__ __nv_bfloat16 g_wvh[C_ * C_], g_wvl[C_ * C_];
__device__ __nv_bfloat16 g_wph[C_ * C_], g_wpl[C_ * C_];

// ---------------- helpers ----------------
__device__ __forceinline__ uint32_t smem_u32(const void* p) {
    uint32_t a;
    asm("{ .reg .u64 t; cvta.to.shared.u64 t, %1; cvt.u32.u64 %0, t; }" : "=r"(a) : "l"(p));
    return a;
}
__device__ __forceinline__ void ldmx4(uint32_t* r, uint32_t addr) {
    asm volatile("ldmatrix.sync.aligned.m8n8.x4.shared.b16 {%0,%1,%2,%3}, [%4];"
                 : "=r"(r[0]), "=r"(r[1]), "=r"(r[2]), "=r"(r[3]) : "r"(addr));
}
__device__ __forceinline__ void ldmx4t(uint32_t* r, uint32_t addr) {
    asm volatile("ldmatrix.sync.aligned.m8n8.x4.trans.shared.b16 {%0,%1,%2,%3}, [%4];"
                 : "=r"(r[0]), "=r"(r[1]), "=r"(r[2]), "=r"(r[3]) : "r"(addr));
}
__device__ __forceinline__ void cp16(uint32_t dst, const void* src) {
    asm volatile("cp.async.cg.shared.global [%0], [%1], 16;" :: "r"(dst), "l"(src));
}
__device__ __forceinline__ void cp_commit() {
    asm volatile("cp.async.commit_group;" ::: "memory");
}
template<int N> __device__ __forceinline__ void cp_wait() {
    asm volatile("cp.async.wait_group %0;" :: "n"(N) : "memory");
}

#define MMA_BF16(acc, a, b0, b1)                                              \
    asm volatile(                                                             \
        "mma.sync.aligned.m16n8k16.row.col.f32.bf16.bf16.f32 "                \
        "{%0,%1,%2,%3},{%4,%5,%6,%7},{%8,%9},{%0,%1,%2,%3};"                  \
        : "+f"((acc)[0]), "+f"((acc)[1]), "+f"((acc)[2]), "+f"((acc)[3])      \
        : "r"((a)[0]), "r"((a)[1]), "r"((a)[2]), "r"((a)[3]),                 \
          "r"(b0), "r"(b1))

__device__ __forceinline__ float gelu_f(float x) {
    return 0.5f * x * (1.f + erff(x * 0.70710678118654752f));
}

// split pair of floats into packed hi/lo bf16x2
__device__ __forceinline__ void split2(float a, float b, uint32_t& h, uint32_t& l) {
    __nv_bfloat16 ha = __float2bfloat16(a), hb = __float2bfloat16(b);
    __nv_bfloat162 hp = __halves2bfloat162(ha, hb);
    __nv_bfloat162 lp = __floats2bfloat162_rn(a - __bfloat162float(ha),
                                              b - __bfloat162float(hb));
    h = *reinterpret_cast<uint32_t*>(&hp);
    l = *reinterpret_cast<uint32_t*>(&lp);
}

// ---------------- elementwise split: fp32 -> hi/lo bf16 --------------------
__global__ __launch_bounds__(256)
void split_act(const float* __restrict__ in, __nv_bfloat16* __restrict__ oh,
               __nv_bfloat16* __restrict__ ol)
{
    const size_t i = (size_t)blockIdx.x * 256 + threadIdx.x;
    float4 v = ((const float4*)in)[i];
    uint32_t h0, l0, h1, l1;
    split2(v.x, v.y, h0, l0);
    split2(v.z, v.w, h1, l1);
    ((uint2*)oh)[i] = make_uint2(h0, h1);
    ((uint2*)ol)[i] = make_uint2(l0, l1);
}

// ---------------- transpose + split: W[R,Cc] -> Wt hi/lo [Cc,R] ------------
__global__ __launch_bounds__(256)
void transpose_split(const float* __restrict__ in,
                     __nv_bfloat16* __restrict__ oh, __nv_bfloat16* __restrict__ ol,
                     int R, int Cc)
{
    __shared__ float t[32][33];
    const int bx = blockIdx.x * 32, by = blockIdx.y * 32;
    const int tx = threadIdx.x & 31, tyq = threadIdx.x >> 5;
    #pragma unroll
    for (int i = tyq; i < 32; i += 8)
        t[i][tx] = in[(size_t)(by + i) * Cc + bx + tx];
    __syncthreads();
    #pragma unroll
    for (int i = tyq; i < 32; i += 8) {
        float v = t[tx][i];
        __nv_bfloat16 h = __float2bfloat16(v);
        oh[(size_t)(bx + i) * R + by + tx] = h;
        ol[(size_t)(bx + i) * R + by + tx] = __float2bfloat16(v - __bfloat162float(h));
    }
}

// ---------------- GEMM: C = A[M,K] @ Bt[N,K]^T (hi/lo bf16, cp.async) ------
// 128x128 tile, 32-K chunks, 3-stage pipeline, SW64-swizzled smem.
constexpr uint32_t G_TILE  = 128 * 64;         // bytes per (array, stage)
constexpr uint32_t G_STAGE = 4 * G_TILE;       // Ah Al Bh Bl = 32768
constexpr uint32_t G_SMEM  = 3 * G_STAGE;      // 98304

__global__ __launch_bounds__(256)
void gemm_cp(const __nv_bfloat16* __restrict__ Ah, const __nv_bfloat16* __restrict__ Al,
             const __nv_bfloat16* __restrict__ Bh, const __nv_bfloat16* __restrict__ Bl,
             const float* __restrict__ bias,
             float* __restrict__ outF,
             __nv_bfloat16* __restrict__ outH, __nv_bfloat16* __restrict__ outL,
             int M, int N, int K, int act, float scale)
{
    extern __shared__ char smem[];
    const uint32_t sb = smem_u32(smem);
    const int tid  = threadIdx.x;
    const int lane = tid & 31;
    const int wid  = tid >> 5;
    const int wm   = wid & 3;
    const int wn   = wid >> 2;
    const int m0   = blockIdx.y * 128;
    const int n0   = blockIdx.x * 128;
    const int NC   = K >> 5;

    float acc[2][8][4];
    #pragma unroll
    for (int i = 0; i < 2; i++)
        #pragma unroll
        for (int j = 0; j < 8; j++)
            #pragma unroll
            for (int t = 0; t < 4; t++) acc[i][j][t] = 0.f;

    // per-thread cp.async slots (8): arr = g>>9, row = (g&511)>>2, seg = g&3
    auto issue = [&](int c) {
        const uint32_t st = sb + (uint32_t)(c % 3) * G_STAGE;
        #pragma unroll
        for (int j = 0; j < 8; j++) {
            const int g   = tid + 256 * j;
            const int arr = g >> 9;
            const int rem = g & 511;
            const int row = rem >> 2;
            const int seg = rem & 3;
            const __nv_bfloat16* src =
                (arr == 0) ? Ah : (arr == 1) ? Al : (arr == 2) ? Bh : Bl;
            const int base = (arr < 2) ? m0 : n0;
            src += (size_t)(base + row) * K + c * 32 + seg * 8;
            const uint32_t dst = st + (uint32_t)arr * G_TILE + row * 64 +
                                 (((uint32_t)(seg ^ ((row >> 1) & 3))) << 4);
            cp16(dst, src);
        }
    };

    issue(0); cp_commit();
    issue(1); cp_commit();
    issue(2); cp_commit();
    cp_wait<2>();
    __syncthreads();

    const uint32_t arow = lane & 15;
    const uint32_t nrow = (lane & 7) | ((lane >> 4) << 3);

    for (int c = 0; c < NC; c++) {
        const uint32_t st = sb + (uint32_t)(c % 3) * G_STAGE;

        #pragma unroll
        for (int kb = 0; kb < 2; kb++) {
            uint32_t ah[2][4], al[2][4];
            const uint32_t sA = kb * 2 + (lane >> 4);
            #pragma unroll
            for (int mi = 0; mi < 2; mi++) {
                const uint32_t r = wm * 32 + arow + mi * 16;
                const uint32_t addr = st + r * 64 + ((sA ^ ((r >> 1) & 3)) << 4);
                ldmx4(ah[mi], addr);
                ldmx4(al[mi], addr + G_TILE);
            }
            const uint32_t sB = kb * 2 + ((lane >> 3) & 1);
            #pragma unroll
            for (int np = 0; np < 4; np++) {
                const uint32_t r = wn * 64 + np * 16 + nrow;
                const uint32_t addr = st + 2 * G_TILE + r * 64 + ((sB ^ ((r >> 1) & 3)) << 4);
                uint32_t bh[4], bl[4];
                ldmx4(bh, addr);
                ldmx4(bl, addr + G_TILE);
                #pragma unroll
                for (int mi = 0; mi < 2; mi++) {
                    #pragma unroll
                    for (int t = 0; t < 2; t++) {
                        float* a4 = acc[mi][np * 2 + t];
                        MMA_BF16(a4, ah[mi], bh[2 * t], bh[2 * t + 1]);
                        MMA_BF16(a4, ah[mi], bl[2 * t], bl[2 * t + 1]);
                        MMA_BF16(a4, al[mi], bh[2 * t], bh[2 * t + 1]);
                    }
                }
            }
        }

        __syncthreads();
        if (c + 3 < NC) { issue(c + 3); cp_commit(); }
        cp_wait<2>();
        __syncthreads();
    }

    // epilogue
    const int rbase = m0 + wm * 32 + (lane >> 2);
    const int cbase = n0 + wn * 64 + (lane & 3) * 2;
    #pragma unroll
    for (int mi = 0; mi < 2; mi++) {
        #pragma unroll
        for (int ni = 0; ni < 8; ni++) {
            const int col = cbase + ni * 8;
            const float bx = bias[col], by = bias[col + 1];
            const int r1 = rbase + mi * 16;
            float v0x = acc[mi][ni][0] + bx, v0y = acc[mi][ni][1] + by;
            float v1x = acc[mi][ni][2] + bx, v1y = acc[mi][ni][3] + by;
            if (act == 1) {
                v0x = gelu_f(v0x); v0y = gelu_f(v0y);
                v1x = gelu_f(v1x); v1y = gelu_f(v1y);
            }
            v0x *= scale; v0y *= scale; v1x *= scale; v1y *= scale;
            if (outF) {
                *(float2*)(outF + (size_t)r1 * N + col)       = make_float2(v0x, v0y);
                *(float2*)(outF + (size_t)(r1 + 8) * N + col) = make_float2(v1x, v1y);
            }
            if (outH) {
                uint32_t h0, l0, h1, l1;
                split2(v0x, v0y, h0, l0);
                split2(v1x, v1y, h1, l1);
                ((uint32_t*)outH)[((size_t)r1 * N + col) >> 1]       = h0;
                ((uint32_t*)outL)[((size_t)r1 * N + col) >> 1]       = l0;
                ((uint32_t*)outH)[((size_t)(r1 + 8) * N + col) >> 1] = h1;
                ((uint32_t*)outL)[((size_t)(r1 + 8) * N + col) >> 1] = l1;
            }
        }
    }
}

// ---------------- LayerNorm + split ----------------------------------------
__global__ __launch_bounds__(256)
void ln_split(const float* __restrict__ in, const float* __restrict__ g,
              const float* __restrict__ b,
              __nv_bfloat16* __restrict__ oh, __nv_bfloat16* __restrict__ ol)
{
    const int row = blockIdx.x;
    const int tid = threadIdx.x;
    float4 v = ((const float4*)(in + (size_t)row * C_))[tid];

    float s  = v.x + v.y + v.z + v.w;
    float s2 = v.x * v.x + v.y * v.y + v.z * v.z + v.w * v.w;
    #pragma unroll
    for (int off = 16; off > 0; off >>= 1) {
        s  += __shfl_xor_sync(0xffffffffu, s,  off);
        s2 += __shfl_xor_sync(0xffffffffu, s2, off);
    }
    __shared__ float sh[16];
    const int w = tid >> 5;
    if ((tid & 31) == 0) { sh[w] = s; sh[w + 8] = s2; }
    __syncthreads();
    if (tid < 32) {
        float a  = (tid < 8) ? sh[tid]     : 0.f;
        float a2 = (tid < 8) ? sh[tid + 8] : 0.f;
        #pragma unroll
        for (int off = 4; off > 0; off >>= 1) {
            a  += __shfl_xor_sync(0xffffffffu, a,  off);
            a2 += __shfl_xor_sync(0xffffffffu, a2, off);
        }
        if (tid == 0) { sh[0] = a; sh[1] = a2; }
    }
    __syncthreads();
    const float mu   = sh[0] * (1.f / C_);
    const float var  = sh[1] * (1.f / C_) - mu * mu;
    const float rstd = rsqrtf(var + 1e-5f);

    float4 gg = ((const float4*)g)[tid];
    float4 bb = ((const float4*)b)[tid];
    float ox = (v.x - mu) * rstd * gg.x + bb.x;
    float oy = (v.y - mu) * rstd * gg.y + bb.y;
    float oz = (v.z - mu) * rstd * gg.z + bb.z;
    float ow = (v.w - mu) * rstd * gg.w + bb.w;
    uint32_t h0, l0, h1, l1;
    split2(ox, oy, h0, l0);
    split2(oz, ow, h1, l1);
    const size_t base = ((size_t)row * C_) >> 1;
    ((uint32_t*)oh)[base + tid * 2]     = h0;
    ((uint32_t*)ol)[base + tid * 2]     = l0;
    ((uint32_t*)oh)[base + tid * 2 + 1] = h1;
    ((uint32_t*)ol)[base + tid * 2 + 1] = l1;
}

// ---------------- Tensor-core flash attention -------------------------------
// 128 q-rows per CTA (8 warps x 16 rows), 64-key iterations, 3-stage cp.async.
// smem: Q hi/lo (2x16KB) | 3 KV stages (Kh Kl Vh Vl, 4x8KB each) | mask floats
constexpr uint32_t A_QT    = 16384;               // per Q array
constexpr uint32_t A_KVT   = 8192;                // per KV array per stage
constexpr uint32_t A_KV0   = 2 * A_QT;            // 32768
constexpr uint32_t A_KVST  = 4 * A_KVT;           // 32768
constexpr uint32_t A_MSK   = A_KV0 + 3 * A_KVST;  // 131072
constexpr uint32_t A_SMEM  = A_MSK + 3 * 64 * 4;  // 131840

__global__ __launch_bounds__(256)
void attn_tc(const __nv_bfloat16* __restrict__ qh, const __nv_bfloat16* __restrict__ ql,
             const __nv_bfloat16* __restrict__ kh, const __nv_bfloat16* __restrict__ kl,
             const __nv_bfloat16* __restrict__ vh, const __nv_bfloat16* __restrict__ vl,
             const int* __restrict__ mask,
             __nv_bfloat16* __restrict__ yh, __nv_bfloat16* __restrict__ yl)
{
    extern __shared__ char smem[];
    const uint32_t sb = smem_u32(smem);
    float* mskp = (float*)(smem + A_MSK);

    const int b   = blockIdx.z;
    const int h   = blockIdx.y;
    const int t0  = blockIdx.x * 128;
    const int tid = threadIdx.x;
    const int lane = tid & 31;
    const int wid  = tid >> 5;

    const size_t qrow0 = (size_t)(b * T_ + t0);
    const size_t krow0 = (size_t)(b * S_);
    const int*   mb    = mask + b * S_;

    auto issueQ = [&]() {
        #pragma unroll
        for (int j = 0; j < 8; j++) {
            const int g   = tid + 256 * j;
            const int arr = g >> 10;
            const int rem = g & 1023;
            const int row = rem >> 3;
            const int seg = rem & 7;
            const __nv_bfloat16* src = (arr ? ql : qh) +
                (qrow0 + row) * C_ + h * D_ + seg * 8;
            const uint32_t dst = sb + (uint32_t)arr * A_QT + row * 128 +
                                 (((uint32_t)(seg ^ (row & 7))) << 4);
            cp16(dst, src);
        }
    };
    auto issueKV = [&](int c) {
        const uint32_t st = sb + A_KV0 + (uint32_t)(c % 3) * A_KVST;
        const int s0 = c * 64;
        #pragma unroll
        for (int j = 0; j < 8; j++) {
            const int g   = tid + 256 * j;
            const int arr = g >> 9;
            const int rem = g & 511;
            const int row = rem >> 3;
            const int seg = rem & 7;
            const __nv_bfloat16* src =
                ((arr == 0) ? kh : (arr == 1) ? kl : (arr == 2) ? vh : vl) +
                (krow0 + s0 + row) * C_ + h * D_ + seg * 8;
            const uint32_t dst = st + (uint32_t)arr * A_KVT + row * 128 +
                                 (((uint32_t)(seg ^ (row & 7))) << 4);
            cp16(dst, src);
        }
        if (tid < 64)
            mskp[(c % 3) * 64 + tid] = mb[s0 + tid] ? 0.f : -1e30f;
    };

    issueQ(); issueKV(0); cp_commit();
    issueKV(1); cp_commit();
    issueKV(2); cp_commit();
    cp_wait<2>();
    __syncthreads();

    // preload Q fragments (hi/lo) for this warp's 16 rows
    uint32_t qfh[4][4], qfl[4][4];
    {
        const uint32_t r = wid * 16 + (lane & 15);
        #pragma unroll
        for (int kc = 0; kc < 4; kc++) {
            const uint32_t s = kc * 2 + (lane >> 4);
            const uint32_t addr = sb + r * 128 + ((s ^ (r & 7)) << 4);
            ldmx4(qfh[kc], addr);
            ldmx4(qfl[kc], addr + A_QT);
        }
    }

    float oacc[8][4];
    #pragma unroll
    for (int i = 0; i < 8; i++)
        #pragma unroll
        for (int t = 0; t < 4; t++) oacc[i][t] = 0.f;
    float m0r = -INFINITY, m1r = -INFINITY, l0r = 0.f, l1r = 0.f;

    const uint32_t nrow = (lane & 7) | ((lane >> 4) << 3);

    for (int c = 0; c < 16; c++) {
        const uint32_t st = sb + A_KV0 + (uint32_t)(c % 3) * A_KVST;
        const float* msks = mskp + (c % 3) * 64;

        // ---- scores = Q K^T (3-pass) ----
        float sc[8][4];
        #pragma unroll
        for (int i = 0; i < 8; i++)
            #pragma unroll
            for (int t = 0; t < 4; t++) sc[i][t] = 0.f;

        #pragma unroll
        for (int kc = 0; kc < 4; kc++) {
            const uint32_t sB = kc * 2 + ((lane >> 3) & 1);
            #pragma unroll
            for (int np = 0; np < 4; np++) {
                const uint32_t r = np * 16 + nrow;
                const uint32_t addr = st + r * 128 + ((sB ^ (r & 7)) << 4);
                uint32_t bh4[4], bl4[4];
                ldmx4(bh4, addr);
                ldmx4(bl4, addr + A_KVT);
                #pragma unroll
                for (int t = 0; t < 2; t++) {
                    float* a4 = sc[np * 2 + t];
                    MMA_BF16(a4, qfh[kc], bh4[2 * t], bh4[2 * t + 1]);
                    MMA_BF16(a4, qfh[kc], bl4[2 * t], bl4[2 * t + 1]);
                    MMA_BF16(a4, qfl[kc], bh4[2 * t], bh4[2 * t + 1]);
                }
            }
        }

        // ---- mask + online softmax ----
        const int cq = (lane & 3) * 2;
        float tmax0 = -INFINITY, tmax1 = -INFINITY;
        #pragma unroll
        for (int nb = 0; nb < 8; nb++) {
            const float ma = msks[nb * 8 + cq];
            const float mbv = msks[nb * 8 + cq + 1];
            sc[nb][0] += ma;  sc[nb][1] += mbv;
            sc[nb][2] += ma;  sc[nb][3] += mbv;
            tmax0 = fmaxf(tmax0, fmaxf(sc[nb][0], sc[nb][1]));
            tmax1 = fmaxf(tmax1, fmaxf(sc[nb][2], sc[nb][3]));
        }
        tmax0 = fmaxf(tmax0, __shfl_xor_sync(0xffffffffu, tmax0, 1));
        tmax0 = fmaxf(tmax0, __shfl_xor_sync(0xffffffffu, tmax0, 2));
        tmax1 = fmaxf(tmax1, __shfl_xor_sync(0xffffffffu, tmax1, 1));
        tmax1 = fmaxf(tmax1, __shfl_xor_sync(0xffffffffu, tmax1, 2));

        const float mn0 = fmaxf(m0r, tmax0);
        const float mn1 = fmaxf(m1r, tmax1);
        const float al0 = __expf(m0r - mn0);
        const float al1 = __expf(m1r - mn1);
        m0r = mn0; m1r = mn1;

        float sum0 = 0.f, sum1 = 0.f;
        #pragma unroll
        for (int nb = 0; nb < 8; nb++) {
            sc[nb][0] = __expf(sc[nb][0] - mn0);
            sc[nb][1] = __expf(sc[nb][1] - mn0);
            sc[nb][2] = __expf(sc[nb][2] - mn1);
            sc[nb][3] = __expf(sc[nb][3] - mn1);
            sum0 += sc[nb][0] + sc[nb][1];
            sum1 += sc[nb][2] + sc[nb][3];
        }
        sum0 += __shfl_xor_sync(0xffffffffu, sum0, 1);
        sum0 += __shfl_xor_sync(0xffffffffu, sum0, 2);
        sum1 += __shfl_xor_sync(0xffffffffu, sum1, 1);
        sum1 += __shfl_xor_sync(0xffffffffu, sum1, 2);
        l0r = l0r * al0 + sum0;
        l1r = l1r * al1 + sum1;
        #pragma unroll
        for (int nd = 0; nd < 8; nd++) {
            oacc[nd][0] *= al0; oacc[nd][1] *= al0;
            oacc[nd][2] *= al1; oacc[nd][3] *= al1;
        }

        // ---- O += P V (3-pass, P repacked from accumulators) ----
        #pragma unroll
        for (int kc = 0; kc < 4; kc++) {
            uint32_t pah[4], pal[4];
            split2(sc[2 * kc][0],     sc[2 * kc][1],     pah[0], pal[0]);
            split2(sc[2 * kc][2],     sc[2 * kc][3],     pah[1], pal[1]);
            split2(sc[2 * kc + 1][0], sc[2 * kc + 1][1], pah[2], pal[2]);
            split2(sc[2 * kc + 1][2], sc[2 * kc + 1][3], pah[3], pal[3]);

            const uint32_t rV = kc * 16 + (lane & 15);
            #pragma unroll
            for (int np = 0; np < 4; np++) {
                const uint32_t sV = np * 2 + (lane >> 4);
                const uint32_t addr = st + 2 * A_KVT + rV * 128 + ((sV ^ (rV & 7)) << 4);
                uint32_t vh4[4], vl4[4];
                ldmx4t(vh4, addr);
                ldmx4t(vl4, addr + A_KVT);
                #pragma unroll
                for (int t = 0; t < 2; t++) {
                    float* a4 = oacc[np * 2 + t];
                    MMA_BF16(a4, pah, vh4[2 * t], vh4[2 * t + 1]);
                    MMA_BF16(a4, pah, vl4[2 * t], vl4[2 * t + 1]);
                    MMA_BF16(a4, pal, vh4[2 * t], vh4[2 * t + 1]);
                }
            }
        }

        __syncthreads();
        if (c + 3 < 16) { issueKV(c + 3); cp_commit(); }
        cp_wait<2>();
        __syncthreads();
    }

    // ---- epilogue: divide by l, split to bf16 hi/lo, store ----
    const float inv0 = 1.f / l0r;
    const float inv1 = 1.f / l1r;
    const size_t row0 = qrow0 + wid * 16 + (lane >> 2);
    const size_t row1 = row0 + 8;
    #pragma unroll
    for (int nd = 0; nd < 8; nd++) {
        const int col = h * D_ + nd * 8 + (lane & 3) * 2;
        uint32_t h0, l0, h1, l1;
        split2(oacc[nd][0] * inv0, oacc[nd][1] * inv0, h0, l0);
        split2(oacc[nd][2] * inv1, oacc[nd][3] * inv1, h1, l1);
        ((uint32_t*)yh)[(row0 * C_ + col) >> 1] = h0;
        ((uint32_t*)yl)[(row0 * C_ + col) >> 1] = l0;
        ((uint32_t*)yh)[(row1 * C_ + col) >> 1] = h1;
        ((uint32_t*)yl)[(row1 * C_ + col) >> 1] = l1;
    }
}

// ---------------- launcher -------------------------------------------------
extern "C" void kernel_launch(void* const* d_in, const int* in_sizes, int n_in,
                              void* d_out, int out_size)
{
    const float* x    = (const float*)d_in[0];
    const float* eemb = (const float*)d_in[1];
    const int*   emsk = (const int*)  d_in[2];
    const float* W1   = (const float*)d_in[3];
    const float* b1   = (const float*)d_in[4];
    const float* W2   = (const float*)d_in[5];
    const float* b2   = (const float*)d_in[6];
    const float* lng  = (const float*)d_in[7];
    const float* lnb  = (const float*)d_in[8];
    const float* Wq   = (const float*)d_in[9];
    const float* bq   = (const float*)d_in[10];
    const float* Wk   = (const float*)d_in[11];
    const float* bk   = (const float*)d_in[12];
    const float* Wv   = (const float*)d_in[13];
    const float* bv   = (const float*)d_in[14];
    const float* Wp   = (const float*)d_in[15];
    const float* bp   = (const float*)d_in[16];
    float* out = (float*)d_out;

    float* tmp;
    cudaGetSymbolAddress((void**)&tmp, g_tmp);
    __nv_bfloat16 *xh,*xl,*eh,*el,*hh,*hl,*ench,*encl,*qh,*ql,*kh,*kl,*vh,*vl,*yh,*yl;
    __nv_bfloat16 *w1h,*w1l,*w2h,*w2l,*wqh,*wql,*wkh,*wkl,*wvh,*wvl,*wph,*wpl;
    cudaGetSymbolAddress((void**)&xh, g_xh);   cudaGetSymbolAddress((void**)&xl, g_xl);
    cudaGetSymbolAddress((void**)&eh, g_eh);   cudaGetSymbolAddress((void**)&el, g_el);
    cudaGetSymbolAddress((void**)&hh, g_hh);   cudaGetSymbolAddress((void**)&hl, g_hl);
    cudaGetSymbolAddress((void**)&ench, g_ench); cudaGetSymbolAddress((void**)&encl, g_encl);
    cudaGetSymbolAddress((void**)&qh, g_qh);   cudaGetSymbolAddress((void**)&ql, g_ql);
    cudaGetSymbolAddress((void**)&kh, g_kh);   cudaGetSymbolAddress((void**)&kl, g_kl);
    cudaGetSymbolAddress((void**)&vh, g_vh);   cudaGetSymbolAddress((void**)&vl, g_vl);
    cudaGetSymbolAddress((void**)&yh, g_yh);   cudaGetSymbolAddress((void**)&yl, g_yl);
    cudaGetSymbolAddress((void**)&w1h, g_w1h); cudaGetSymbolAddress((void**)&w1l, g_w1l);
    cudaGetSymbolAddress((void**)&w2h, g_w2h); cudaGetSymbolAddress((void**)&w2l, g_w2l);
    cudaGetSymbolAddress((void**)&wqh, g_wqh); cudaGetSymbolAddress((void**)&wql, g_wql);
    cudaGetSymbolAddress((void**)&wkh, g_wkh); cudaGetSymbolAddress((void**)&wkl, g_wkl);
    cudaGetSymbolAddress((void**)&wvh, g_wvh); cudaGetSymbolAddress((void**)&wvl, g_wvl);
    cudaGetSymbolAddress((void**)&wph, g_wph); cudaGetSymbolAddress((void**)&wpl, g_wpl);

    cudaFuncSetAttribute(gemm_cp, cudaFuncAttributeMaxDynamicSharedMemorySize, G_SMEM);
    cudaFuncSetAttribute(attn_tc, cudaFuncAttributeMaxDynamicSharedMemorySize, A_SMEM);

    // input splits
    split_act<<<MQ * C_ / 1024, 256>>>(x, xh, xl);
    split_act<<<ME * E_ / 1024, 256>>>(eemb, eh, el);

    // weight transpose + split
    transpose_split<<<dim3(C_ / 32, E_ / 32), 256>>>(W1, w1h, w1l, E_, C_);
    transpose_split<<<dim3(C_ / 32, C_ / 32), 256>>>(W2, w2h, w2l, C_, C_);
    transpose_split<<<dim3(C_ / 32, C_ / 32), 256>>>(Wq, wqh, wql, C_, C_);
    transpose_split<<<dim3(C_ / 32, C_ / 32), 256>>>(Wk, wkh, wkl, C_, C_);
    transpose_split<<<dim3(C_ / 32, C_ / 32), 256>>>(Wv, wvh, wvl, C_, C_);
    transpose_split<<<dim3(C_ / 32, C_ / 32), 256>>>(Wp, wph, wpl, C_, C_);

    // encoder MLP
    gemm_cp<<<dim3(C_ / 128, ME / 128), 256, G_SMEM>>>(
        eh, el, w1h, w1l, b1, nullptr, hh, hl, ME, C_, E_, 1, 1.f);
    gemm_cp<<<dim3(C_ / 128, ME / 128), 256, G_SMEM>>>(
        hh, hl, w2h, w2l, b2, tmp, nullptr, nullptr, ME, C_, C_, 0, 1.f);
    ln_split<<<ME, 256>>>(tmp, lng, lnb, ench, encl);

    // projections (softmax scale folded into Q)
    gemm_cp<<<dim3(C_ / 128, MQ / 128), 256, G_SMEM>>>(
        xh, xl, wqh, wql, bq, nullptr, qh, ql, MQ, C_, C_, 0, 0.125f);
    gemm_cp<<<dim3(C_ / 128, ME / 128), 256, G_SMEM>>>(
        ench, encl, wkh, wkl, bk, nullptr, kh, kl, ME, C_, C_, 0, 1.f);
    gemm_cp<<<dim3(C_ / 128, ME / 128), 256, G_SMEM>>>(
        ench, encl, wvh, wvl, bv, nullptr, vh, vl, ME, C_, C_, 0, 1.f);

    // attention
    attn_tc<<<dim3(T_ / 128, 16, B_), 256, A_SMEM>>>(
        qh, ql, kh, kl, vh, vl, emsk, yh, yl);

    // output projection
    gemm_cp<<<dim3(C_ / 128, MQ / 128), 256, G_SMEM>>>(
        yh, yl, wph, wpl, bp, out, nullptr, nullptr, MQ, C_, C_, 0, 1.f);
}